// round 2
// baseline (speedup 1.0000x reference)
#include <cuda_runtime.h>
#include <math.h>

// SignedAttention: B=4, H=8, L=2048, D=64
// pid = pos/16; query attends keys with 1 <= pid_k - pid_q <= 9  (window <= 144 keys)
// A = softmax(scale*s) - softmax(-scale*s) over the window; masked terms underflow to 0.

#define BH     32          // B*H
#define LSEQ   2048
#define DDIM   64
#define NPATCH 128
#define CHAN   16
#define WIN    10
#define WMAX   144         // 9 patches * 16

#define SQ_STRIDE 68       // padded row strides (floats) to dodge bank conflicts
#define SK_STRIDE 68
#define SS_STRIDE 145

#define SMEM_FLOATS (16*SQ_STRIDE + WMAX*SK_STRIDE + WMAX*SK_STRIDE + 16*SS_STRIDE)
#define SMEM_BYTES  (SMEM_FLOATS * 4)

__global__ void __launch_bounds__(256, 2)
signed_attn_kernel(const float* __restrict__ Q,
                   const float* __restrict__ K,
                   const float* __restrict__ V,
                   const float* __restrict__ log_scale,
                   float* __restrict__ O)
{
    extern __shared__ float sm[];
    float* sQ = sm;                              // [16][SQ_STRIDE]
    float* sK = sQ + 16 * SQ_STRIDE;             // [WMAX][SK_STRIDE]
    float* sV = sK + WMAX * SK_STRIDE;           // [WMAX][SK_STRIDE]
    float* sS = sV + WMAX * SK_STRIDE;           // [16][SS_STRIDE]

    const int p   = blockIdx.x;                  // query patch 0..127
    const int bh  = blockIdx.y;                  // 0..31
    const int tid = threadIdx.x;

    const int qrow0  = bh * LSEQ + p * CHAN;     // first query row (of 64 floats)
    const int kstart = (p + 1) * CHAN;
    const int kend   = min((p + WIN) * CHAN, LSEQ);
    const int W      = kend - kstart;

    if (W <= 0) {
        // fully masked rows -> exact zeros (uniform - uniform in reference)
        int q  = tid >> 4;
        int dc = (tid & 15) * 4;
        *(float4*)&O[(qrow0 + q) * DDIM + dc] = make_float4(0.f, 0.f, 0.f, 0.f);
        return;
    }

    const float scale = fminf(fmaxf(__expf(log_scale[0]), 1.0f), 30.0f) * 0.125f; // /sqrt(64)

    // ---- stage Q (16x64) ----
    {
        int r = tid >> 4;
        int c = (tid & 15) * 4;
        float4 v = *(const float4*)&Q[(qrow0 + r) * DDIM + c];
        *(float4*)&sQ[r * SQ_STRIDE + c] = v;
    }
    // ---- stage K,V (Wx64) ----
    const int krow0 = bh * LSEQ + kstart;
    for (int idx = tid; idx < W * 16; idx += 256) {
        int r = idx >> 4;
        int c = (idx & 15) * 4;
        *(float4*)&sK[r * SK_STRIDE + c] = *(const float4*)&K[(krow0 + r) * DDIM + c];
        *(float4*)&sV[r * SK_STRIDE + c] = *(const float4*)&V[(krow0 + r) * DDIM + c];
    }
    __syncthreads();

    // ---- scores: thread (tq, tg) computes s[tq][tg + 16*jj], jj = 0..8 ----
    // Within a warp: 16 tq x 2 tg -> K row reads are 16-way broadcast (conflict-free).
    {
        const int tq = tid & 15;
        const int tg = tid >> 4;
        float acc[9];
#pragma unroll
        for (int jj = 0; jj < 9; jj++) acc[jj] = 0.f;
        const int nj = (W - tg + 15) >> 4;       // >= 1 since W >= 16
#pragma unroll
        for (int c = 0; c < 16; c++) {
            float4 qv = *(float4*)&sQ[tq * SQ_STRIDE + c * 4];
#pragma unroll
            for (int jj = 0; jj < 9; jj++) {
                if (jj < nj) {
                    float4 kv = *(float4*)&sK[(tg + jj * 16) * SK_STRIDE + c * 4];
                    acc[jj] += qv.x * kv.x + qv.y * kv.y + qv.z * kv.z + qv.w * kv.w;
                }
            }
        }
#pragma unroll
        for (int jj = 0; jj < 9; jj++)
            if (jj < nj) sS[tq * SS_STRIDE + tg + jj * 16] = acc[jj];
    }
    __syncthreads();

    // ---- signed double softmax: warp w handles rows 2w, 2w+1; 16 lanes per row ----
    {
        const int lane = tid & 31;
        const int row  = (tid >> 5) * 2 + (lane >> 4);
        const int l16  = lane & 15;

        float mx = -1e30f, mn = 1e30f;
        for (int j = l16; j < W; j += 16) {
            float s = sS[row * SS_STRIDE + j];
            mx = fmaxf(mx, s);
            mn = fminf(mn, s);
        }
#pragma unroll
        for (int o = 8; o > 0; o >>= 1) {
            mx = fmaxf(mx, __shfl_xor_sync(0xffffffffu, mx, o));
            mn = fminf(mn, __shfl_xor_sync(0xffffffffu, mn, o));
        }
        float sp = 0.f, sn = 0.f;
        for (int j = l16; j < W; j += 16) {
            float s = sS[row * SS_STRIDE + j];
            sp += __expf(scale * (s - mx));
            sn += __expf(scale * (mn - s));
        }
#pragma unroll
        for (int o = 8; o > 0; o >>= 1) {
            sp += __shfl_xor_sync(0xffffffffu, sp, o);
            sn += __shfl_xor_sync(0xffffffffu, sn, o);
        }
        const float rp = 1.0f / sp;
        const float rn = 1.0f / sn;
        for (int j = l16; j < W; j += 16) {
            float s = sS[row * SS_STRIDE + j];
            sS[row * SS_STRIDE + j] =
                __expf(scale * (s - mx)) * rp - __expf(scale * (mn - s)) * rn;
        }
    }
    __syncthreads();

    // ---- AV: thread (q, dc) accumulates 4 output dims ----
    {
        const int q  = tid >> 4;
        const int dc = (tid & 15) * 4;
        float4 acc = make_float4(0.f, 0.f, 0.f, 0.f);
        const float* sSrow = &sS[q * SS_STRIDE];
#pragma unroll 4
        for (int j = 0; j < W; j++) {
            float a  = sSrow[j];
            float4 v = *(float4*)&sV[j * SK_STRIDE + dc];
            acc.x += a * v.x;
            acc.y += a * v.y;
            acc.z += a * v.z;
            acc.w += a * v.w;
        }
        *(float4*)&O[(qrow0 + q) * DDIM + dc] = acc;
    }
}

extern "C" void kernel_launch(void* const* d_in, const int* in_sizes, int n_in,
                              void* d_out, int out_size)
{
    const float* Q  = (const float*)d_in[0];
    const float* K  = (const float*)d_in[1];
    const float* V  = (const float*)d_in[2];
    const float* ls = (const float*)d_in[3];
    float* O        = (float*)d_out;

    cudaFuncSetAttribute(signed_attn_kernel,
                         cudaFuncAttributeMaxDynamicSharedMemorySize, SMEM_BYTES);

    dim3 grid(NPATCH, BH);   // 128 x 32 = 4096 CTAs
    signed_attn_kernel<<<grid, 256, SMEM_BYTES>>>(Q, K, V, ls, O);
}

// round 3
// speedup vs baseline: 1.3356x; 1.3356x over previous
#include <cuda_runtime.h>
#include <math.h>

// SignedAttention: B=4, H=8, L=2048, D=64
// pid = pos/16; query attends keys with 1 <= pid_k - pid_q <= 9  (window <= 144 keys)
// A = softmax(scale*s) - softmax(-scale*s) over the window; masked terms underflow to 0.

#define BH     32
#define LSEQ   2048
#define DDIM   64
#define NPATCH 128
#define CHAN   16
#define WIN    10
#define WMAX   144

#define SQ_STRIDE 68     // floats; 272B rows (16B aligned, conflict-benign)
#define SK_STRIDE 68
#define SA_STRIDE 20     // transposed A: [j][16 q], padded; 80B rows (16B aligned)

#define SQ_OFF 0
#define SK_OFF (16 * SQ_STRIDE)
#define SV_OFF (SK_OFF + WMAX * SK_STRIDE)
#define SA_OFF (SV_OFF + WMAX * SK_STRIDE)
#define SMEM_FLOATS (SA_OFF + WMAX * SA_STRIDE)
#define SMEM_BYTES  (SMEM_FLOATS * 4)
#define PS_OFF SK_OFF    // psum [4][16][SK_STRIDE] aliases dead sK region

typedef unsigned long long ull;

__device__ __forceinline__ ull ffma2(ull a, ull b, ull c) {
    ull d;
    asm("fma.rn.f32x2 %0, %1, %2, %3;" : "=l"(d) : "l"(a), "l"(b), "l"(c));
    return d;
}
__device__ __forceinline__ ull splat2(float f) {
    ull d;
    asm("mov.b64 %0, {%1, %1};" : "=l"(d) : "f"(f));
    return d;
}
__device__ __forceinline__ float2 unpk(ull v) {
    float lo, hi;
    asm("mov.b64 {%0, %1}, %2;" : "=f"(lo), "=f"(hi) : "l"(v));
    return make_float2(lo, hi);
}

__global__ void __launch_bounds__(256, 2)
signed_attn_kernel(const float* __restrict__ Q,
                   const float* __restrict__ K,
                   const float* __restrict__ V,
                   const float* __restrict__ log_scale,
                   float* __restrict__ O)
{
    extern __shared__ float sm[];

    const int p   = blockIdx.x;      // query patch
    const int bh  = blockIdx.y;
    const int tid = threadIdx.x;

    const int qrow0  = bh * LSEQ + p * CHAN;
    const int kstart = (p + 1) * CHAN;
    const int kend   = min((p + WIN) * CHAN, LSEQ);
    const int W      = kend - kstart;         // multiple of 16 (or 0)

    if (W <= 0) {   // fully masked -> exact zeros
        int q  = tid >> 4;
        int dc = (tid & 15) * 4;
        *(float4*)&O[(qrow0 + q) * DDIM + dc] = make_float4(0.f, 0.f, 0.f, 0.f);
        return;
    }

    const float scale = fminf(fmaxf(__expf(log_scale[0]), 1.0f), 30.0f) * 0.125f;

    // ---- stage Q (16x64) ----
    {
        int r = tid >> 4;
        int c = (tid & 15) * 4;
        *(float4*)&sm[SQ_OFF + r * SQ_STRIDE + c] =
            *(const float4*)&Q[(qrow0 + r) * DDIM + c];
    }
    // ---- stage K, V (Wx64) ----
    const int krow0 = bh * LSEQ + kstart;
    for (int idx = tid; idx < W * 16; idx += 256) {
        int r = idx >> 4;
        int c = (idx & 15) * 4;
        *(float4*)&sm[SK_OFF + r * SK_STRIDE + c] = *(const float4*)&K[(krow0 + r) * DDIM + c];
        *(float4*)&sm[SV_OFF + r * SK_STRIDE + c] = *(const float4*)&V[(krow0 + r) * DDIM + c];
    }
    __syncthreads();

    // ---- scores: thread (tqp, kt) computes rows {2tqp, 2tqp+1} x keys {kt+32jj} ----
    // Warp lanes: tqp 0..7 x kt in 4 consecutive values -> K loads are 8-way
    // broadcast (1 wavefront), Q loads 8 distinct (1 wavefront). f32x2 FMA over
    // paired k-dims: 2 FFMA2 per float4 chunk per (row, key).
    {
        const int tqp = tid & 7;
        const int kt  = tid >> 3;                     // 0..31
        const int NJ  = (kt < W) ? ((W - kt + 31) >> 5) : 0;   // <= 5, warp-uniform

        ull accp[2][5];
#pragma unroll
        for (int r = 0; r < 2; r++)
#pragma unroll
            for (int jj = 0; jj < 5; jj++) accp[r][jj] = 0ull;

        const ulonglong2* q0p = (const ulonglong2*)&sm[SQ_OFF + (2 * tqp) * SQ_STRIDE];
        const ulonglong2* q1p = (const ulonglong2*)&sm[SQ_OFF + (2 * tqp + 1) * SQ_STRIDE];

#pragma unroll
        for (int c2 = 0; c2 < 16; c2++) {             // 16 float4 chunks of D=64
            ulonglong2 q0 = q0p[c2];
            ulonglong2 q1 = q1p[c2];
#pragma unroll
            for (int jj = 0; jj < 5; jj++) {
                if (jj < NJ) {
                    ulonglong2 kv =
                        *(const ulonglong2*)&sm[SK_OFF + (kt + 32 * jj) * SK_STRIDE + c2 * 4];
                    accp[0][jj] = ffma2(q0.x, kv.x, accp[0][jj]);
                    accp[0][jj] = ffma2(q0.y, kv.y, accp[0][jj]);
                    accp[1][jj] = ffma2(q1.x, kv.x, accp[1][jj]);
                    accp[1][jj] = ffma2(q1.y, kv.y, accp[1][jj]);
                }
            }
        }
        // store scores transposed: sA[j][q]
#pragma unroll
        for (int jj = 0; jj < 5; jj++) {
            if (jj < NJ) {
                float2 a0 = unpk(accp[0][jj]);
                float2 a1 = unpk(accp[1][jj]);
                int jrow = SA_OFF + (kt + 32 * jj) * SA_STRIDE;
                sm[jrow + 2 * tqp]     = a0.x + a0.y;
                sm[jrow + 2 * tqp + 1] = a1.x + a1.y;
            }
        }
    }
    __syncthreads();

    // ---- signed double softmax over transposed scores ----
    // warp w handles rows 2w, 2w+1; 16 lanes per row scan j = l16 + 16i.
    {
        const int lane = tid & 31;
        const int row  = (tid >> 5) * 2 + (lane >> 4);
        const int l16  = lane & 15;

        float mx = -1e30f, mn = 1e30f;
        for (int j = l16; j < W; j += 16) {
            float s = sm[SA_OFF + j * SA_STRIDE + row];
            mx = fmaxf(mx, s);
            mn = fminf(mn, s);
        }
#pragma unroll
        for (int o = 8; o > 0; o >>= 1) {
            mx = fmaxf(mx, __shfl_xor_sync(0xffffffffu, mx, o));
            mn = fminf(mn, __shfl_xor_sync(0xffffffffu, mn, o));
        }
        float sp = 0.f, sn = 0.f;
        for (int j = l16; j < W; j += 16) {
            float s = sm[SA_OFF + j * SA_STRIDE + row];
            sp += __expf(scale * (s - mx));
            sn += __expf(scale * (mn - s));
        }
#pragma unroll
        for (int o = 8; o > 0; o >>= 1) {
            sp += __shfl_xor_sync(0xffffffffu, sp, o);
            sn += __shfl_xor_sync(0xffffffffu, sn, o);
        }
        const float rp = 1.0f / sp;
        const float rn = 1.0f / sn;
        for (int j = l16; j < W; j += 16) {
            float s = sm[SA_OFF + j * SA_STRIDE + row];
            sm[SA_OFF + j * SA_STRIDE + row] =
                __expf(scale * (s - mx)) * rp - __expf(scale * (mn - s)) * rn;
        }
    }
    __syncthreads();

    // ---- AV: 4 groups split W; thread = (group g, q4, dc) covers 4 queries x 4 dims ----
    // A loads: one LDS.128 gives 4 queries' A at row j (pairs over queries for f32x2).
    {
        const int g  = tid >> 6;          // 0..3
        const int dc = tid & 15;          // dim column (x4)
        const int q4 = (tid >> 4) & 3;    // query quad

        const int JC = W >> 2;            // W is a multiple of 16
        const int j0 = g * JC;
        const int j1 = j0 + JC;

        ull acc[2][4];
#pragma unroll
        for (int qp = 0; qp < 2; qp++)
#pragma unroll
            for (int d = 0; d < 4; d++) acc[qp][d] = 0ull;

        for (int j = j0; j < j1; j++) {
            ulonglong2 ap = *(const ulonglong2*)&sm[SA_OFF + j * SA_STRIDE + q4 * 4];
            float4 vv = *(const float4*)&sm[SV_OFF + j * SK_STRIDE + dc * 4];
            ull v0 = splat2(vv.x), v1 = splat2(vv.y), v2 = splat2(vv.z), v3 = splat2(vv.w);
            acc[0][0] = ffma2(ap.x, v0, acc[0][0]);
            acc[0][1] = ffma2(ap.x, v1, acc[0][1]);
            acc[0][2] = ffma2(ap.x, v2, acc[0][2]);
            acc[0][3] = ffma2(ap.x, v3, acc[0][3]);
            acc[1][0] = ffma2(ap.y, v0, acc[1][0]);
            acc[1][1] = ffma2(ap.y, v1, acc[1][1]);
            acc[1][2] = ffma2(ap.y, v2, acc[1][2]);
            acc[1][3] = ffma2(ap.y, v3, acc[1][3]);
        }

        // partial sums into psum[g][q][dc*4..] (aliases dead sK region)
#pragma unroll
        for (int qp = 0; qp < 2; qp++) {
            float2 u0 = unpk(acc[qp][0]);
            float2 u1 = unpk(acc[qp][1]);
            float2 u2 = unpk(acc[qp][2]);
            float2 u3 = unpk(acc[qp][3]);
            int qe = q4 * 4 + qp * 2;
            *(float4*)&sm[PS_OFF + (g * 16 + qe) * SK_STRIDE + dc * 4] =
                make_float4(u0.x, u1.x, u2.x, u3.x);
            *(float4*)&sm[PS_OFF + (g * 16 + qe + 1) * SK_STRIDE + dc * 4] =
                make_float4(u0.y, u1.y, u2.y, u3.y);
        }
    }
    __syncthreads();

    // ---- reduce 4 partials and store ----
    {
        const int q  = tid >> 4;
        const int dc = (tid & 15) * 4;
        float4 r = make_float4(0.f, 0.f, 0.f, 0.f);
#pragma unroll
        for (int g = 0; g < 4; g++) {
            float4 t = *(const float4*)&sm[PS_OFF + (g * 16 + q) * SK_STRIDE + dc];
            r.x += t.x; r.y += t.y; r.z += t.z; r.w += t.w;
        }
        *(float4*)&O[(qrow0 + q) * DDIM + dc] = r;
    }
}

extern "C" void kernel_launch(void* const* d_in, const int* in_sizes, int n_in,
                              void* d_out, int out_size)
{
    const float* Q  = (const float*)d_in[0];
    const float* K  = (const float*)d_in[1];
    const float* V  = (const float*)d_in[2];
    const float* ls = (const float*)d_in[3];
    float* O        = (float*)d_out;

    cudaFuncSetAttribute(signed_attn_kernel,
                         cudaFuncAttributeMaxDynamicSharedMemorySize, SMEM_BYTES);

    dim3 grid(NPATCH, BH);
    signed_attn_kernel<<<grid, 256, SMEM_BYTES>>>(Q, K, V, ls, O);
}

// round 14
// speedup vs baseline: 2.3777x; 1.7802x over previous
#include <cuda_runtime.h>
#include <cuda_fp16.h>
#include <stdint.h>
#include <math.h>

// SignedAttention via warp-level HMMA (mma.sync.m16n8k16), fp16 hi/lo split.
// CTA = (bh, 8 patches); warp = 1 patch: 16 queries x <=144-key window.

#define SM_KH 0                 // K hi: [256 keys][72 halves] = 36864 B
#define SM_KL 36864             // K lo
#define SM_VH 73728             // V hi, pair-interleaved: [128 pairs][144 halves] = 36864 B
#define SM_VL 110592            // V lo
#define SM_S  147456            // per-warp scratch: 8 x [16][148] f32 = 75776 B
#define S_STRIDE 148            // words per row (=20 mod 32 -> conflict-free)
#define S_WARP   (16 * S_STRIDE)
#define SMEM_BYTES (SM_S + 8 * S_WARP * 4)   // 223232

__device__ __forceinline__ void mma16816(float d[4], const uint32_t a[4],
                                         const uint32_t b[2]) {
    asm volatile(
        "mma.sync.aligned.m16n8k16.row.col.f32.f16.f16.f32 "
        "{%0,%1,%2,%3}, {%4,%5,%6,%7}, {%8,%9}, {%0,%1,%2,%3};"
        : "+f"(d[0]), "+f"(d[1]), "+f"(d[2]), "+f"(d[3])
        : "r"(a[0]), "r"(a[1]), "r"(a[2]), "r"(a[3]), "r"(b[0]), "r"(b[1]));
}
__device__ __forceinline__ uint32_t prmt(uint32_t a, uint32_t b, uint32_t s) {
    uint32_t d;
    asm("prmt.b32 %0, %1, %2, %3;" : "=r"(d) : "r"(a), "r"(b), "r"(s));
    return d;
}
// pack a as (fp16 hi | fp16 residual << 16)
__device__ __forceinline__ uint32_t packA(float a) {
    __half h = __float2half_rn(a);
    __half l = __float2half_rn(a - __half2float(h));
    return (uint32_t)__half_as_ushort(h) | ((uint32_t)__half_as_ushort(l) << 16);
}

__global__ void __launch_bounds__(256, 1)
signed_attn_hmma(const float* __restrict__ Q, const float* __restrict__ K,
                 const float* __restrict__ V, const float* __restrict__ LS,
                 float* __restrict__ O)
{
    extern __shared__ char smem[];
    const int tid = threadIdx.x, wid = tid >> 5, lane = tid & 31;
    const int g = lane >> 2, t = lane & 3;     // mma quad coords
    const int p0 = blockIdx.x * 8, bh = blockIdx.y;
    const int kstart = (p0 + 1) * 16;
    const int Kv = min(256, 2048 - kstart);    // staged valid keys

    // ---- stage K (row-major, 72-half pad) and V (key-pair interleaved), hi/lo ----
    // 256 rows x 32 dim-pairs = 8192 items; 256 threads -> 32 iterations.
    const float* Kg = K + (bh * 2048 + kstart) * 64;
    const float* Vg = V + (bh * 2048 + kstart) * 64;
    #pragma unroll
    for (int it = 0; it < 32; it++) {
        int r = wid + 8 * it;                  // staged key row (warp-uniform)
        int c = lane;                          // dim pair
        float2 kv = (r < Kv) ? *(const float2*)&Kg[r * 64 + 2 * c] : make_float2(0.f, 0.f);
        float2 vv = (r < Kv) ? *(const float2*)&Vg[r * 64 + 2 * c] : make_float2(0.f, 0.f);
        __half2 kh = __floats2half2_rn(kv.x, kv.y);
        float2 kf = __half22float2(kh);
        __half2 kl = __floats2half2_rn(kv.x - kf.x, kv.y - kf.y);
        __half2 vh = __floats2half2_rn(vv.x, vv.y);
        float2 vf = __half22float2(vh);
        __half2 vl = __floats2half2_rn(vv.x - vf.x, vv.y - vf.y);
        *(__half2*)(smem + SM_KH + r * 144 + 4 * c) = kh;
        *(__half2*)(smem + SM_KL + r * 144 + 4 * c) = kl;
        int vb = (r >> 1) * 288 + (r & 1) * 2;         // pair row, parity
        *(__half*)(smem + SM_VH + vb + 8 * c)     = __low2half(vh);
        *(__half*)(smem + SM_VH + vb + 8 * c + 4) = __high2half(vh);
        *(__half*)(smem + SM_VL + vb + 8 * c)     = __low2half(vl);
        *(__half*)(smem + SM_VL + vb + 8 * c + 4) = __high2half(vl);
    }
    // ---- stage this warp's Q (fp32) into its S region ----
    float* Sw = (float*)(smem + SM_S) + wid * S_WARP;
    const float* Qg = Q + (bh * 2048 + p0 * 16 + wid * 16) * 64;
    #pragma unroll
    for (int u = 0; u < 8; u++) {
        int chunk = lane + 32 * u;
        int row = chunk >> 4, c4 = chunk & 15;
        *(float4*)&Sw[row * S_STRIDE + 4 * c4] = *(const float4*)&Qg[row * 64 + 4 * c4];
    }
    __syncthreads();

    const int p  = p0 + wid;
    const int Wp = min(144, 2048 - (p + 1) * 16);  // window length (mult of 16, or <=0)
    const int obase = bh * 2048 + p * 16;
    if (Wp <= 0) {                                  // patch 127: fully masked -> zeros
        int row = lane >> 1, c0 = (lane & 1) * 32;
        #pragma unroll
        for (int u = 0; u < 8; u++)
            *(float4*)&O[(obase + row) * 64 + c0 + 4 * u] = make_float4(0.f, 0.f, 0.f, 0.f);
        return;
    }
    const float scale = fminf(fmaxf(__expf(LS[0]), 1.f), 30.f) * 0.125f;

    // ---- Q fragments (hi/lo), 4 k-steps ----
    uint32_t qh[4][4], ql[4][4];
    #pragma unroll
    for (int ks = 0; ks < 4; ks++) {
        #pragma unroll
        for (int q = 0; q < 4; q++) {
            int rr = (q & 1) ? g + 8 : g;
            int cc = 16 * ks + 2 * t + ((q >= 2) ? 8 : 0);
            float2 v = *(float2*)&Sw[rr * S_STRIDE + cc];
            __half2 h = __floats2half2_rn(v.x, v.y);
            float2 f = __half22float2(h);
            __half2 l = __floats2half2_rn(v.x - f.x, v.y - f.y);
            qh[ks][q] = *(uint32_t*)&h;
            ql[ks][q] = *(uint32_t*)&l;
        }
    }

    // ---- scores: 18 n-tiles (8 keys) x 4 k-steps x 3 hi/lo MMAs ----
    const int nTiles = Wp >> 3;
    float sD[18][4];
    #pragma unroll
    for (int i = 0; i < 18; i++) { sD[i][0] = sD[i][1] = sD[i][2] = sD[i][3] = 0.f; }
    const char* khp = smem + SM_KH + (16 * wid + g) * 144 + 4 * t;
    const char* klp = smem + SM_KL + (16 * wid + g) * 144 + 4 * t;
    #pragma unroll
    for (int nt = 0; nt < 18; nt++) {
        if (nt < nTiles) {
            #pragma unroll
            for (int ks = 0; ks < 4; ks++) {
                uint32_t bhf[2], blf[2];
                bhf[0] = *(const uint32_t*)(khp + nt * 1152 + ks * 32);
                bhf[1] = *(const uint32_t*)(khp + nt * 1152 + ks * 32 + 16);
                blf[0] = *(const uint32_t*)(klp + nt * 1152 + ks * 32);
                blf[1] = *(const uint32_t*)(klp + nt * 1152 + ks * 32 + 16);
                mma16816(sD[nt], qh[ks], bhf);
                mma16816(sD[nt], ql[ks], bhf);
                mma16816(sD[nt], qh[ks], blf);
            }
        }
    }

    // ---- in-register signed double softmax (rows g and g+8; quad reduce) ----
    float mx0 = -1e30f, mn0 = 1e30f, mx8 = -1e30f, mn8 = 1e30f;
    #pragma unroll
    for (int nt = 0; nt < 18; nt++) if (nt < nTiles) {
        mx0 = fmaxf(mx0, fmaxf(sD[nt][0], sD[nt][1]));
        mn0 = fminf(mn0, fminf(sD[nt][0], sD[nt][1]));
        mx8 = fmaxf(mx8, fmaxf(sD[nt][2], sD[nt][3]));
        mn8 = fminf(mn8, fminf(sD[nt][2], sD[nt][3]));
    }
    #pragma unroll
    for (int o = 1; o <= 2; o <<= 1) {
        mx0 = fmaxf(mx0, __shfl_xor_sync(~0u, mx0, o));
        mn0 = fminf(mn0, __shfl_xor_sync(~0u, mn0, o));
        mx8 = fmaxf(mx8, __shfl_xor_sync(~0u, mx8, o));
        mn8 = fminf(mn8, __shfl_xor_sync(~0u, mn8, o));
    }
    float sp0 = 0.f, sn0 = 0.f, sp8 = 0.f, sn8 = 0.f;
    #pragma unroll
    for (int nt = 0; nt < 18; nt++) if (nt < nTiles) {
        sp0 += __expf(scale * (sD[nt][0] - mx0)) + __expf(scale * (sD[nt][1] - mx0));
        sn0 += __expf(scale * (mn0 - sD[nt][0])) + __expf(scale * (mn0 - sD[nt][1]));
        sp8 += __expf(scale * (sD[nt][2] - mx8)) + __expf(scale * (sD[nt][3] - mx8));
        sn8 += __expf(scale * (mn8 - sD[nt][2])) + __expf(scale * (mn8 - sD[nt][3]));
    }
    #pragma unroll
    for (int o = 1; o <= 2; o <<= 1) {
        sp0 += __shfl_xor_sync(~0u, sp0, o);
        sn0 += __shfl_xor_sync(~0u, sn0, o);
        sp8 += __shfl_xor_sync(~0u, sp8, o);
        sn8 += __shfl_xor_sync(~0u, sn8, o);
    }
    const float rp0 = 1.0f / sp0, rn0 = 1.0f / sn0;
    const float rp8 = 1.0f / sp8, rn8 = 1.0f / sn8;

    // ---- write A = ep*rp - en*rn packed (hi|lo) to S ----
    #pragma unroll
    for (int nt = 0; nt < 18; nt++) if (nt < nTiles) {
        float a0 = __expf(scale * (sD[nt][0] - mx0)) * rp0 - __expf(scale * (mn0 - sD[nt][0])) * rn0;
        float a1 = __expf(scale * (sD[nt][1] - mx0)) * rp0 - __expf(scale * (mn0 - sD[nt][1])) * rn0;
        float a2 = __expf(scale * (sD[nt][2] - mx8)) * rp8 - __expf(scale * (mn8 - sD[nt][2])) * rn8;
        float a3 = __expf(scale * (sD[nt][3] - mx8)) * rp8 - __expf(scale * (mn8 - sD[nt][3])) * rn8;
        *(uint2*)&Sw[g * S_STRIDE + 8 * nt + 2 * t]       = make_uint2(packA(a0), packA(a1));
        *(uint2*)&Sw[(g + 8) * S_STRIDE + 8 * nt + 2 * t] = make_uint2(packA(a2), packA(a3));
    }
    __syncwarp();

    // ---- AV: D[16x64] = (Ah+Al) x (Vh+Vl), 9 k-steps x 8 n-tiles ----
    const int kSteps = Wp >> 4;
    float oD[8][4];
    #pragma unroll
    for (int i = 0; i < 8; i++) { oD[i][0] = oD[i][1] = oD[i][2] = oD[i][3] = 0.f; }
    const char* vhp = smem + SM_VH + (8 * wid + t) * 288 + 4 * g;
    const char* vlp = smem + SM_VL + (8 * wid + t) * 288 + 4 * g;
    #pragma unroll
    for (int ks = 0; ks < 9; ks++) {
        if (ks < kSteps) {
            uint2 w01 = *(uint2*)&Sw[g * S_STRIDE + 16 * ks + 2 * t];
            uint2 w23 = *(uint2*)&Sw[(g + 8) * S_STRIDE + 16 * ks + 2 * t];
            uint2 w45 = *(uint2*)&Sw[g * S_STRIDE + 16 * ks + 2 * t + 8];
            uint2 w67 = *(uint2*)&Sw[(g + 8) * S_STRIDE + 16 * ks + 2 * t + 8];
            uint32_t Ah[4], Al[4];
            Ah[0] = prmt(w01.x, w01.y, 0x5410); Al[0] = prmt(w01.x, w01.y, 0x7632);
            Ah[1] = prmt(w23.x, w23.y, 0x5410); Al[1] = prmt(w23.x, w23.y, 0x7632);
            Ah[2] = prmt(w45.x, w45.y, 0x5410); Al[2] = prmt(w45.x, w45.y, 0x7632);
            Ah[3] = prmt(w67.x, w67.y, 0x5410); Al[3] = prmt(w67.x, w67.y, 0x7632);
            #pragma unroll
            for (int nt2 = 0; nt2 < 8; nt2++) {
                uint32_t bhf[2], blf[2];
                bhf[0] = *(const uint32_t*)(vhp + ks * 2304 + nt2 * 32);
                bhf[1] = *(const uint32_t*)(vhp + ks * 2304 + nt2 * 32 + 1152);
                blf[0] = *(const uint32_t*)(vlp + ks * 2304 + nt2 * 32);
                blf[1] = *(const uint32_t*)(vlp + ks * 2304 + nt2 * 32 + 1152);
                mma16816(oD[nt2], Ah, bhf);
                mma16816(oD[nt2], Al, bhf);
                mma16816(oD[nt2], Ah, blf);
            }
        }
    }

    // ---- store O ----
    #pragma unroll
    for (int nt2 = 0; nt2 < 8; nt2++) {
        *(float2*)&O[(obase + g) * 64 + 8 * nt2 + 2 * t]     = make_float2(oD[nt2][0], oD[nt2][1]);
        *(float2*)&O[(obase + g + 8) * 64 + 8 * nt2 + 2 * t] = make_float2(oD[nt2][2], oD[nt2][3]);
    }
}

extern "C" void kernel_launch(void* const* d_in, const int* in_sizes, int n_in,
                              void* d_out, int out_size)
{
    const float* Q  = (const float*)d_in[0];
    const float* K  = (const float*)d_in[1];
    const float* V  = (const float*)d_in[2];
    const float* ls = (const float*)d_in[3];
    float* O        = (float*)d_out;

    cudaFuncSetAttribute(signed_attn_hmma,
                         cudaFuncAttributeMaxDynamicSharedMemorySize, SMEM_BYTES);

    dim3 grid(16, 32);   // 16 patch groups x 32 bh
    signed_attn_hmma<<<grid, 256, SMEM_BYTES>>>(Q, K, V, ls, O);
}

// round 15
// speedup vs baseline: 2.6867x; 1.1300x over previous
#include <cuda_runtime.h>
#include <cuda_fp16.h>
#include <stdint.h>
#include <math.h>

// SignedAttention via warp-pair HMMA. CTA = (bh, 8 patches), 16 warps:
// warp pair per patch; halves split keys for scores, dims for AV.

#define SM_KH 0                 // K hi: [256 keys][72 halves] = 36864 B
#define SM_KL 36864             // K lo
#define SM_VH 73728             // V hi, key-pair interleaved: [128 pairs][144 halves]
#define SM_VL 110592            // V lo
#define SM_A  147456            // A packed per patch: 8 x [16][148] u32 = 75776 B
#define A_STRIDE 148
#define A_PATCH  (16 * A_STRIDE)
#define SM_ST (SM_A + 8 * A_PATCH * 4)       // stats: 8p x 2rnd x 2h x 16row x 8B = 4096
#define SMEM_BYTES (SM_ST + 4096)            // 227328

__device__ __forceinline__ void mma16816(float d[4], const uint32_t a[4],
                                         const uint32_t b[2]) {
    asm volatile(
        "mma.sync.aligned.m16n8k16.row.col.f32.f16.f16.f32 "
        "{%0,%1,%2,%3}, {%4,%5,%6,%7}, {%8,%9}, {%0,%1,%2,%3};"
        : "+f"(d[0]), "+f"(d[1]), "+f"(d[2]), "+f"(d[3])
        : "r"(a[0]), "r"(a[1]), "r"(a[2]), "r"(a[3]), "r"(b[0]), "r"(b[1]));
}
__device__ __forceinline__ uint32_t prmt(uint32_t a, uint32_t b, uint32_t s) {
    uint32_t d;
    asm("prmt.b32 %0, %1, %2, %3;" : "=r"(d) : "r"(a), "r"(b), "r"(s));
    return d;
}
__device__ __forceinline__ uint32_t packA(float a) {
    __half h = __float2half_rn(a);
    __half l = __float2half_rn(a - __half2float(h));
    return (uint32_t)__half_as_ushort(h) | ((uint32_t)__half_as_ushort(l) << 16);
}
#define PAIR_BAR(id) asm volatile("bar.sync %0, 64;" :: "r"(id) : "memory")

__global__ void __launch_bounds__(512, 1)
signed_attn_hmma2(const float* __restrict__ Q, const float* __restrict__ K,
                  const float* __restrict__ V, const float* __restrict__ LS,
                  float* __restrict__ O)
{
    extern __shared__ char smem[];
    const int tid = threadIdx.x, wid = tid >> 5, lane = tid & 31;
    const int g = lane >> 2, t = lane & 3;
    const int pl = wid >> 1;             // patch local 0..7
    const int h  = wid & 1;              // key/dim half
    const int p0 = blockIdx.x * 8, bh = blockIdx.y;
    const int kstart = (p0 + 1) * 16;
    const int Kv = min(256, 2048 - kstart);

    // ---- stage K/V hi/lo: 256 rows x 32 dim-pairs, 512 threads -> 16 iters ----
    const float* Kg = K + (bh * 2048 + kstart) * 64;
    const float* Vg = V + (bh * 2048 + kstart) * 64;
    #pragma unroll
    for (int it = 0; it < 16; it++) {
        int r = wid + 16 * it;
        int c = lane;
        float2 kv = (r < Kv) ? *(const float2*)&Kg[r * 64 + 2 * c] : make_float2(0.f, 0.f);
        float2 vv = (r < Kv) ? *(const float2*)&Vg[r * 64 + 2 * c] : make_float2(0.f, 0.f);
        __half2 kh = __floats2half2_rn(kv.x, kv.y);
        float2 kf = __half22float2(kh);
        __half2 kl = __floats2half2_rn(kv.x - kf.x, kv.y - kf.y);
        __half2 vh = __floats2half2_rn(vv.x, vv.y);
        float2 vf = __half22float2(vh);
        __half2 vl = __floats2half2_rn(vv.x - vf.x, vv.y - vf.y);
        *(__half2*)(smem + SM_KH + r * 144 + 4 * c) = kh;
        *(__half2*)(smem + SM_KL + r * 144 + 4 * c) = kl;
        int vb = (r >> 1) * 288 + (r & 1) * 2;
        *(__half*)(smem + SM_VH + vb + 8 * c)     = __low2half(vh);
        *(__half*)(smem + SM_VH + vb + 8 * c + 4) = __high2half(vh);
        *(__half*)(smem + SM_VL + vb + 8 * c)     = __low2half(vl);
        *(__half*)(smem + SM_VL + vb + 8 * c + 4) = __high2half(vl);
    }
    __syncthreads();

    const int p  = p0 + pl;
    const int Wp = min(144, 2048 - (p + 1) * 16);
    const int obase = bh * 2048 + p * 16;
    if (Wp <= 0) {   // patch 127: zeros (each warp stores its 32-dim half)
        int row = lane >> 1, c0 = 32 * h + (lane & 1) * 16;
        #pragma unroll
        for (int u = 0; u < 4; u++)
            *(float4*)&O[(obase + row) * 64 + c0 + 4 * u] = make_float4(0.f, 0.f, 0.f, 0.f);
        return;
    }
    const float scale = fminf(fmaxf(__expf(LS[0]), 1.f), 30.f) * 0.125f;

    // ---- Q fragments (hi/lo) straight from gmem ----
    const float* Qg = Q + (bh * 2048 + p * 16) * 64;
    uint32_t qh[4][4], ql[4][4];
    #pragma unroll
    for (int ks = 0; ks < 4; ks++) {
        #pragma unroll
        for (int q = 0; q < 4; q++) {
            int rr = (q & 1) ? g + 8 : g;
            int cc = 16 * ks + 2 * t + ((q >= 2) ? 8 : 0);
            float2 v = *(const float2*)&Qg[rr * 64 + cc];
            __half2 hh = __floats2half2_rn(v.x, v.y);
            float2 f = __half22float2(hh);
            __half2 ll = __floats2half2_rn(v.x - f.x, v.y - f.y);
            qh[ks][q] = *(uint32_t*)&hh;
            ql[ks][q] = *(uint32_t*)&ll;
        }
    }

    // ---- scores: this warp's 72-key half = up to 9 n-tiles ----
    const int nTl = max(0, min(9, (Wp - 72 * h) >> 3));
    float sD[9][4];
    #pragma unroll
    for (int i = 0; i < 9; i++) { sD[i][0] = sD[i][1] = sD[i][2] = sD[i][3] = 0.f; }
    const char* khp = smem + SM_KH + (16 * pl + 72 * h + g) * 144 + 4 * t;
    const char* klp = smem + SM_KL + (16 * pl + 72 * h + g) * 144 + 4 * t;
    #pragma unroll
    for (int nt = 0; nt < 9; nt++) {
        if (nt < nTl) {
            #pragma unroll
            for (int ks = 0; ks < 4; ks++) {
                uint32_t bhf[2], blf[2];
                bhf[0] = *(const uint32_t*)(khp + nt * 1152 + ks * 32);
                bhf[1] = *(const uint32_t*)(khp + nt * 1152 + ks * 32 + 16);
                blf[0] = *(const uint32_t*)(klp + nt * 1152 + ks * 32);
                blf[1] = *(const uint32_t*)(klp + nt * 1152 + ks * 32 + 16);
                mma16816(sD[nt], qh[ks], bhf);
                mma16816(sD[nt], ql[ks], bhf);
                mma16816(sD[nt], qh[ks], blf);
            }
        }
    }

    // ---- partial row max/min (rows g, g+8), quad reduce ----
    float mx0 = -1e30f, mn0 = 1e30f, mx8 = -1e30f, mn8 = 1e30f;
    #pragma unroll
    for (int nt = 0; nt < 9; nt++) if (nt < nTl) {
        mx0 = fmaxf(mx0, fmaxf(sD[nt][0], sD[nt][1]));
        mn0 = fminf(mn0, fminf(sD[nt][0], sD[nt][1]));
        mx8 = fmaxf(mx8, fmaxf(sD[nt][2], sD[nt][3]));
        mn8 = fminf(mn8, fminf(sD[nt][2], sD[nt][3]));
    }
    #pragma unroll
    for (int o = 1; o <= 2; o <<= 1) {
        mx0 = fmaxf(mx0, __shfl_xor_sync(~0u, mx0, o));
        mn0 = fminf(mn0, __shfl_xor_sync(~0u, mn0, o));
        mx8 = fmaxf(mx8, __shfl_xor_sync(~0u, mx8, o));
        mn8 = fminf(mn8, __shfl_xor_sync(~0u, mn8, o));
    }
    // exchange with pair warp (round 0)
    float2* st0 = (float2*)(smem + SM_ST + ((pl * 2 + 0) * 2 + 0) * 128);
    float2* st1 = (float2*)(smem + SM_ST + ((pl * 2 + 0) * 2 + 1) * 128);
    {
        float2* stw = h ? st1 : st0;
        if (t == 0) { stw[g] = make_float2(mx0, mn0); stw[g + 8] = make_float2(mx8, mn8); }
    }
    PAIR_BAR(1 + pl);
    {
        float2 a = st0[g],     b = st1[g];
        mx0 = fmaxf(a.x, b.x); mn0 = fminf(a.y, b.y);
        float2 c = st0[g + 8], d = st1[g + 8];
        mx8 = fmaxf(c.x, d.x); mn8 = fminf(c.y, d.y);
    }

    // ---- partial exp sums with global max/min ----
    float sp0 = 0.f, sn0 = 0.f, sp8 = 0.f, sn8 = 0.f;
    #pragma unroll
    for (int nt = 0; nt < 9; nt++) if (nt < nTl) {
        sp0 += __expf(scale * (sD[nt][0] - mx0)) + __expf(scale * (sD[nt][1] - mx0));
        sn0 += __expf(scale * (mn0 - sD[nt][0])) + __expf(scale * (mn0 - sD[nt][1]));
        sp8 += __expf(scale * (sD[nt][2] - mx8)) + __expf(scale * (sD[nt][3] - mx8));
        sn8 += __expf(scale * (mn8 - sD[nt][2])) + __expf(scale * (mn8 - sD[nt][3]));
    }
    #pragma unroll
    for (int o = 1; o <= 2; o <<= 1) {
        sp0 += __shfl_xor_sync(~0u, sp0, o);
        sn0 += __shfl_xor_sync(~0u, sn0, o);
        sp8 += __shfl_xor_sync(~0u, sp8, o);
        sn8 += __shfl_xor_sync(~0u, sn8, o);
    }
    float2* su0 = (float2*)(smem + SM_ST + ((pl * 2 + 1) * 2 + 0) * 128);
    float2* su1 = (float2*)(smem + SM_ST + ((pl * 2 + 1) * 2 + 1) * 128);
    {
        float2* suw = h ? su1 : su0;
        if (t == 0) { suw[g] = make_float2(sp0, sn0); suw[g + 8] = make_float2(sp8, sn8); }
    }
    PAIR_BAR(1 + pl);
    float rp0, rn0, rp8, rn8;
    {
        float2 a = su0[g],     b = su1[g];
        rp0 = 1.0f / (a.x + b.x); rn0 = 1.0f / (a.y + b.y);
        float2 c = su0[g + 8], d = su1[g + 8];
        rp8 = 1.0f / (c.x + d.x); rn8 = 1.0f / (c.y + d.y);
    }

    // ---- write A = ep*rp - en*rn (hi|lo packed) into shared patch region ----
    uint32_t* Apat = (uint32_t*)(smem + SM_A) + pl * A_PATCH;
    #pragma unroll
    for (int nt = 0; nt < 9; nt++) if (nt < nTl) {
        float a0 = __expf(scale * (sD[nt][0] - mx0)) * rp0 - __expf(scale * (mn0 - sD[nt][0])) * rn0;
        float a1 = __expf(scale * (sD[nt][1] - mx0)) * rp0 - __expf(scale * (mn0 - sD[nt][1])) * rn0;
        float a2 = __expf(scale * (sD[nt][2] - mx8)) * rp8 - __expf(scale * (mn8 - sD[nt][2])) * rn8;
        float a3 = __expf(scale * (sD[nt][3] - mx8)) * rp8 - __expf(scale * (mn8 - sD[nt][3])) * rn8;
        int kk = 72 * h + 8 * nt + 2 * t;
        *(uint2*)&Apat[g * A_STRIDE + kk]       = make_uint2(packA(a0), packA(a1));
        *(uint2*)&Apat[(g + 8) * A_STRIDE + kk] = make_uint2(packA(a2), packA(a3));
    }
    PAIR_BAR(1 + pl);   // A fully written by both halves

    // ---- AV: all keys x this warp's 32-dim half (4 n-tiles) ----
    const int kSteps = Wp >> 4;
    float oD[4][4];
    #pragma unroll
    for (int i = 0; i < 4; i++) { oD[i][0] = oD[i][1] = oD[i][2] = oD[i][3] = 0.f; }
    const char* vhp = smem + SM_VH + (8 * pl + t) * 288 + 4 * g + 32 * (4 * h);
    const char* vlp = smem + SM_VL + (8 * pl + t) * 288 + 4 * g + 32 * (4 * h);
    #pragma unroll
    for (int ks = 0; ks < 9; ks++) {
        if (ks < kSteps) {
            uint2 w01 = *(uint2*)&Apat[g * A_STRIDE + 16 * ks + 2 * t];
            uint2 w23 = *(uint2*)&Apat[(g + 8) * A_STRIDE + 16 * ks + 2 * t];
            uint2 w45 = *(uint2*)&Apat[g * A_STRIDE + 16 * ks + 2 * t + 8];
            uint2 w67 = *(uint2*)&Apat[(g + 8) * A_STRIDE + 16 * ks + 2 * t + 8];
            uint32_t Ah[4], Al[4];
            Ah[0] = prmt(w01.x, w01.y, 0x5410); Al[0] = prmt(w01.x, w01.y, 0x7632);
            Ah[1] = prmt(w23.x, w23.y, 0x5410); Al[1] = prmt(w23.x, w23.y, 0x7632);
            Ah[2] = prmt(w45.x, w45.y, 0x5410); Al[2] = prmt(w45.x, w45.y, 0x7632);
            Ah[3] = prmt(w67.x, w67.y, 0x5410); Al[3] = prmt(w67.x, w67.y, 0x7632);
            #pragma unroll
            for (int j = 0; j < 4; j++) {
                uint32_t bhf[2], blf[2];
                bhf[0] = *(const uint32_t*)(vhp + ks * 2304 + j * 32);
                bhf[1] = *(const uint32_t*)(vhp + ks * 2304 + j * 32 + 1152);
                blf[0] = *(const uint32_t*)(vlp + ks * 2304 + j * 32);
                blf[1] = *(const uint32_t*)(vlp + ks * 2304 + j * 32 + 1152);
                mma16816(oD[j], Ah, bhf);
                mma16816(oD[j], Al, bhf);
                mma16816(oD[j], Ah, blf);
            }
        }
    }

    // ---- store O (this warp's 32 dims) ----
    #pragma unroll
    for (int j = 0; j < 4; j++) {
        int dbase = 8 * (4 * h + j) + 2 * t;
        *(float2*)&O[(obase + g) * 64 + dbase]     = make_float2(oD[j][0], oD[j][1]);
        *(float2*)&O[(obase + g + 8) * 64 + dbase] = make_float2(oD[j][2], oD[j][3]);
    }
}

extern "C" void kernel_launch(void* const* d_in, const int* in_sizes, int n_in,
                              void* d_out, int out_size)
{
    const float* Q  = (const float*)d_in[0];
    const float* K  = (const float*)d_in[1];
    const float* V  = (const float*)d_in[2];
    const float* ls = (const float*)d_in[3];
    float* O        = (float*)d_out;

    cudaFuncSetAttribute(signed_attn_hmma2,
                         cudaFuncAttributeMaxDynamicSharedMemorySize, SMEM_BYTES);

    dim3 grid(16, 32);
    signed_attn_hmma2<<<grid, 512, SMEM_BYTES>>>(Q, K, V, ls, O);
}

// round 16
// speedup vs baseline: 3.4287x; 1.2762x over previous
#include <cuda_runtime.h>
#include <cuda_fp16.h>
#include <stdint.h>
#include <math.h>

// SignedAttention, warp-pair HMMA. CTA = (bh, 4 patches), 8 warps, 2 CTAs/SM.
// K fp16 hi/lo (accurate scores); V and A single fp16. A aliased over dead K.

#define NK 192                         // staged keys (union of 4 windows)
#define SM_KH 0                        // [192][144B] = 27648
#define SM_KL 27648                    // 27648
#define SM_VH 55296                    // [96 pairs][288B] = 27648
#define SM_ST 82944                    // stats: r1 1024 + r2 1024
#define SMEM_BYTES (SM_ST + 2048)      // 84992 -> 2 CTAs/SM
#define A_STRIDE 76                    // u32 per row (72 + pad)
#define A_PATCH  (16 * A_STRIDE)       // 1216 u32 = 4864 B; 4 patches in dead KH

__device__ __forceinline__ void mma16816(float d[4], const uint32_t a[4],
                                         const uint32_t b[2]) {
    asm volatile(
        "mma.sync.aligned.m16n8k16.row.col.f32.f16.f16.f32 "
        "{%0,%1,%2,%3}, {%4,%5,%6,%7}, {%8,%9}, {%0,%1,%2,%3};"
        : "+f"(d[0]), "+f"(d[1]), "+f"(d[2]), "+f"(d[3])
        : "r"(a[0]), "r"(a[1]), "r"(a[2]), "r"(a[3]), "r"(b[0]), "r"(b[1]));
}
__device__ __forceinline__ uint32_t packA2(float a, float b) {
    __half2 h = __floats2half2_rn(a, b);
    return *reinterpret_cast<uint32_t*>(&h);
}
#define PAIR_BAR(id) asm volatile("bar.sync %0, 64;" :: "r"(id) : "memory")

__global__ void __launch_bounds__(256, 2)
signed_attn_hmma3(const float* __restrict__ Q, const float* __restrict__ K,
                  const float* __restrict__ V, const float* __restrict__ LS,
                  float* __restrict__ O)
{
    extern __shared__ char smem[];
    const int tid = threadIdx.x, wid = tid >> 5, lane = tid & 31;
    const int g = lane >> 2, t = lane & 3;
    const int pl = wid >> 1;             // patch local 0..3
    const int h  = wid & 1;              // key half (scores) / dim half (AV)
    const int p0 = blockIdx.x * 4, bh = blockIdx.y;
    const int kstart = (p0 + 1) * 16;
    const int Kv = min(NK, 2048 - kstart);

    // ---- stage K hi/lo + V hi: 192 rows x 32 dim-pairs, 256 thr -> 24 iters ----
    const float* Kg = K + (bh * 2048 + kstart) * 64;
    const float* Vg = V + (bh * 2048 + kstart) * 64;
    #pragma unroll
    for (int it = 0; it < 24; it++) {
        int r = wid + 8 * it;            // warp-uniform row
        int c = lane;                    // dim pair
        float2 kv = (r < Kv) ? *(const float2*)&Kg[r * 64 + 2 * c] : make_float2(0.f, 0.f);
        float2 vv = (r < Kv) ? *(const float2*)&Vg[r * 64 + 2 * c] : make_float2(0.f, 0.f);
        __half2 kh = __floats2half2_rn(kv.x, kv.y);
        float2 kf = __half22float2(kh);
        __half2 kl = __floats2half2_rn(kv.x - kf.x, kv.y - kf.y);
        __half2 vh = __floats2half2_rn(vv.x, vv.y);
        *(__half2*)(smem + SM_KH + r * 144 + 4 * c) = kh;
        *(__half2*)(smem + SM_KL + r * 144 + 4 * c) = kl;
        int vb = (r >> 1) * 288 + (r & 1) * 2;       // key-pair interleave
        *(__half*)(smem + SM_VH + vb + 8 * c)     = __low2half(vh);
        *(__half*)(smem + SM_VH + vb + 8 * c + 4) = __high2half(vh);
    }
    __syncthreads();

    const int p  = p0 + pl;
    const int Wp = min(144, 2048 - (p + 1) * 16);   // 0 only for p=127
    const int obase = bh * 2048 + p * 16;
    const float scale = fminf(fmaxf(__expf(LS[0]), 1.f), 30.f) * 0.125f;

    // ---- Q fragments (hi/lo) straight from gmem ----
    const float* Qg = Q + (bh * 2048 + p * 16) * 64;
    uint32_t qh[4][4], ql[4][4];
    #pragma unroll
    for (int ks = 0; ks < 4; ks++) {
        #pragma unroll
        for (int q = 0; q < 4; q++) {
            int rr = (q & 1) ? g + 8 : g;
            int cc = 16 * ks + 2 * t + ((q >= 2) ? 8 : 0);
            float2 v = *(const float2*)&Qg[rr * 64 + cc];
            __half2 hh = __floats2half2_rn(v.x, v.y);
            float2 f = __half22float2(hh);
            __half2 ll = __floats2half2_rn(v.x - f.x, v.y - f.y);
            qh[ks][q] = *(uint32_t*)&hh;
            ql[ks][q] = *(uint32_t*)&ll;
        }
    }

    // ---- scores: this warp's 72-key half (<=9 n-tiles), 3-MMA hi/lo ----
    const int nTl = max(0, min(9, (Wp - 72 * h) >> 3));
    float sD[9][4];
    #pragma unroll
    for (int i = 0; i < 9; i++) { sD[i][0] = sD[i][1] = sD[i][2] = sD[i][3] = 0.f; }
    const char* khp = smem + SM_KH + (16 * pl + 72 * h + g) * 144 + 4 * t;
    const char* klp = smem + SM_KL + (16 * pl + 72 * h + g) * 144 + 4 * t;
    #pragma unroll
    for (int nt = 0; nt < 9; nt++) {
        if (nt < nTl) {
            #pragma unroll
            for (int ks = 0; ks < 4; ks++) {
                uint32_t bhf[2], blf[2];
                bhf[0] = *(const uint32_t*)(khp + nt * 1152 + ks * 32);
                bhf[1] = *(const uint32_t*)(khp + nt * 1152 + ks * 32 + 16);
                blf[0] = *(const uint32_t*)(klp + nt * 1152 + ks * 32);
                blf[1] = *(const uint32_t*)(klp + nt * 1152 + ks * 32 + 16);
                mma16816(sD[nt], qh[ks], bhf);
                mma16816(sD[nt], ql[ks], bhf);
                mma16816(sD[nt], qh[ks], blf);
            }
        }
    }

    // ---- partial row max/min (rows g, g+8), quad reduce ----
    float mx0 = -1e30f, mn0 = 1e30f, mx8 = -1e30f, mn8 = 1e30f;
    #pragma unroll
    for (int nt = 0; nt < 9; nt++) if (nt < nTl) {
        mx0 = fmaxf(mx0, fmaxf(sD[nt][0], sD[nt][1]));
        mn0 = fminf(mn0, fminf(sD[nt][0], sD[nt][1]));
        mx8 = fmaxf(mx8, fmaxf(sD[nt][2], sD[nt][3]));
        mn8 = fminf(mn8, fminf(sD[nt][2], sD[nt][3]));
    }
    #pragma unroll
    for (int o = 1; o <= 2; o <<= 1) {
        mx0 = fmaxf(mx0, __shfl_xor_sync(~0u, mx0, o));
        mn0 = fminf(mn0, __shfl_xor_sync(~0u, mn0, o));
        mx8 = fmaxf(mx8, __shfl_xor_sync(~0u, mx8, o));
        mn8 = fminf(mn8, __shfl_xor_sync(~0u, mn8, o));
    }
    // r1 exchange; __syncthreads doubles as "K region dead" barrier for A alias
    float2* r1w = (float2*)(smem + SM_ST + pl * 256 + h * 128);
    if (t == 0) { r1w[g] = make_float2(mx0, mn0); r1w[g + 8] = make_float2(mx8, mn8); }
    __syncthreads();
    {
        float2* r10 = (float2*)(smem + SM_ST + pl * 256);
        float2* r11 = (float2*)(smem + SM_ST + pl * 256 + 128);
        float2 a = r10[g],     b = r11[g];
        mx0 = fmaxf(a.x, b.x); mn0 = fminf(a.y, b.y);
        float2 c = r10[g + 8], d = r11[g + 8];
        mx8 = fmaxf(c.x, d.x); mn8 = fminf(c.y, d.y);
    }

    // ---- partial exp sums with global max/min ----
    float sp0 = 0.f, sn0 = 0.f, sp8 = 0.f, sn8 = 0.f;
    #pragma unroll
    for (int nt = 0; nt < 9; nt++) if (nt < nTl) {
        sp0 += __expf(scale * (sD[nt][0] - mx0)) + __expf(scale * (sD[nt][1] - mx0));
        sn0 += __expf(scale * (mn0 - sD[nt][0])) + __expf(scale * (mn0 - sD[nt][1]));
        sp8 += __expf(scale * (sD[nt][2] - mx8)) + __expf(scale * (sD[nt][3] - mx8));
        sn8 += __expf(scale * (mn8 - sD[nt][2])) + __expf(scale * (mn8 - sD[nt][3]));
    }
    #pragma unroll
    for (int o = 1; o <= 2; o <<= 1) {
        sp0 += __shfl_xor_sync(~0u, sp0, o);
        sn0 += __shfl_xor_sync(~0u, sn0, o);
        sp8 += __shfl_xor_sync(~0u, sp8, o);
        sn8 += __shfl_xor_sync(~0u, sn8, o);
    }
    float2* r2w = (float2*)(smem + SM_ST + 1024 + pl * 256 + h * 128);
    if (t == 0) { r2w[g] = make_float2(sp0, sn0); r2w[g + 8] = make_float2(sp8, sn8); }
    PAIR_BAR(1 + pl);
    float rp0, rn0, rp8, rn8;
    {
        float2* r20 = (float2*)(smem + SM_ST + 1024 + pl * 256);
        float2* r21 = (float2*)(smem + SM_ST + 1024 + pl * 256 + 128);
        float2 a = r20[g],     b = r21[g];
        rp0 = 1.0f / (a.x + b.x); rn0 = 1.0f / (a.y + b.y);
        float2 c = r20[g + 8], d = r21[g + 8];
        rp8 = 1.0f / (c.x + d.x); rn8 = 1.0f / (c.y + d.y);
    }

    // ---- write A (single fp16, 2 keys/word) into dead-K region ----
    uint32_t* Apat = (uint32_t*)smem + pl * A_PATCH;
    #pragma unroll
    for (int nt = 0; nt < 9; nt++) if (nt < nTl) {
        float a0 = __expf(scale * (sD[nt][0] - mx0)) * rp0 - __expf(scale * (mn0 - sD[nt][0])) * rn0;
        float a1 = __expf(scale * (sD[nt][1] - mx0)) * rp0 - __expf(scale * (mn0 - sD[nt][1])) * rn0;
        float a2 = __expf(scale * (sD[nt][2] - mx8)) * rp8 - __expf(scale * (mn8 - sD[nt][2])) * rn8;
        float a3 = __expf(scale * (sD[nt][3] - mx8)) * rp8 - __expf(scale * (mn8 - sD[nt][3])) * rn8;
        int wc = 36 * h + 4 * nt + t;                 // packed word column
        Apat[g * A_STRIDE + wc]       = packA2(a0, a1);
        Apat[(g + 8) * A_STRIDE + wc] = packA2(a2, a3);
    }
    PAIR_BAR(1 + pl);    // A complete for this patch

    // ---- AV: all keys x this warp's 32-dim half; A-words ARE a-frags ----
    const int kSteps = max(0, Wp) >> 4;
    float oD[4][4];
    #pragma unroll
    for (int i = 0; i < 4; i++) { oD[i][0] = oD[i][1] = oD[i][2] = oD[i][3] = 0.f; }
    const char* vhp = smem + SM_VH + (8 * pl + t) * 288 + 4 * g + 128 * h;
    #pragma unroll
    for (int ks = 0; ks < 9; ks++) {
        if (ks < kSteps) {
            uint32_t a[4];
            a[0] = Apat[g * A_STRIDE + 8 * ks + t];
            a[1] = Apat[(g + 8) * A_STRIDE + 8 * ks + t];
            a[2] = Apat[g * A_STRIDE + 8 * ks + 4 + t];
            a[3] = Apat[(g + 8) * A_STRIDE + 8 * ks + 4 + t];
            #pragma unroll
            for (int j = 0; j < 4; j++) {
                uint32_t b[2];
                b[0] = *(const uint32_t*)(vhp + ks * 2304 + j * 32);
                b[1] = *(const uint32_t*)(vhp + ks * 2304 + j * 32 + 1152);
                mma16816(oD[j], a, b);
            }
        }
    }

    // ---- store O (this warp's 32 dims); zeros for p=127 ----
    #pragma unroll
    for (int j = 0; j < 4; j++) {
        int dbase = 8 * (4 * h + j) + 2 * t;
        *(float2*)&O[(obase + g) * 64 + dbase]     = make_float2(oD[j][0], oD[j][1]);
        *(float2*)&O[(obase + g + 8) * 64 + dbase] = make_float2(oD[j][2], oD[j][3]);
    }
}

extern "C" void kernel_launch(void* const* d_in, const int* in_sizes, int n_in,
                              void* d_out, int out_size)
{
    const float* Q  = (const float*)d_in[0];
    const float* K  = (const float*)d_in[1];
    const float* V  = (const float*)d_in[2];
    const float* ls = (const float*)d_in[3];
    float* O        = (float*)d_out;

    cudaFuncSetAttribute(signed_attn_hmma3,
                         cudaFuncAttributeMaxDynamicSharedMemorySize, SMEM_BYTES);

    dim3 grid(32, 32);   // 32 patch groups x 32 bh = 1024 CTAs
    signed_attn_hmma3<<<grid, 256, SMEM_BYTES>>>(Q, K, V, ls, O);
}

// round 17
// speedup vs baseline: 4.2352x; 1.2352x over previous
#include <cuda_runtime.h>
#include <cuda_fp16.h>
#include <stdint.h>
#include <math.h>

// SignedAttention, warp-pair HMMA. CTA = (bh, 4 patches), 8 warps, 3 CTAs/SM.
// Q fp16 hi/lo, K/V/A single fp16. A aliased over dead K region.

#define NK 192                         // staged keys (union of 4 windows)
#define SM_KH 0                        // K fp16: [192][144B] = 27648
#define SM_VH 27648                    // V fp16, key-pair interleaved: 27648
#define SM_ST 55296                    // stats: r1 1024 + r2 1024
#define SMEM_BYTES (SM_ST + 2048)      // 57344 -> 3 CTAs/SM (with <=85 regs)
#define A_STRIDE 76                    // u32 per row (72 + pad)
#define A_PATCH  (16 * A_STRIDE)       // 4864 B x4 patches = 19456 < 27648 (dead K)

__device__ __forceinline__ void mma16816(float d[4], const uint32_t a[4],
                                         const uint32_t b[2]) {
    asm volatile(
        "mma.sync.aligned.m16n8k16.row.col.f32.f16.f16.f32 "
        "{%0,%1,%2,%3}, {%4,%5,%6,%7}, {%8,%9}, {%0,%1,%2,%3};"
        : "+f"(d[0]), "+f"(d[1]), "+f"(d[2]), "+f"(d[3])
        : "r"(a[0]), "r"(a[1]), "r"(a[2]), "r"(a[3]), "r"(b[0]), "r"(b[1]));
}
__device__ __forceinline__ uint32_t packA2(float a, float b) {
    __half2 h = __floats2half2_rn(a, b);
    return *reinterpret_cast<uint32_t*>(&h);
}
#define PAIR_BAR(id) asm volatile("bar.sync %0, 64;" :: "r"(id) : "memory")

__global__ void __launch_bounds__(256, 3)
signed_attn_hmma4(const float* __restrict__ Q, const float* __restrict__ K,
                  const float* __restrict__ V, const float* __restrict__ LS,
                  float* __restrict__ O)
{
    extern __shared__ char smem[];
    const int tid = threadIdx.x, wid = tid >> 5, lane = tid & 31;
    const int g = lane >> 2, t = lane & 3;
    const int pl = wid >> 1;             // patch local 0..3
    const int h  = wid & 1;              // key half (scores) / dim half (AV)
    const int p0 = blockIdx.x * 4, bh = blockIdx.y;
    const int kstart = (p0 + 1) * 16;
    const int Kv = min(NK, 2048 - kstart);

    // ---- stage K fp16 + V fp16: 192 rows x 32 dim-pairs, 256 thr -> 24 iters ----
    const float* Kg = K + (bh * 2048 + kstart) * 64;
    const float* Vg = V + (bh * 2048 + kstart) * 64;
    #pragma unroll
    for (int it = 0; it < 24; it++) {
        int r = wid + 8 * it;            // warp-uniform row
        int c = lane;                    // dim pair
        float2 kv = (r < Kv) ? *(const float2*)&Kg[r * 64 + 2 * c] : make_float2(0.f, 0.f);
        float2 vv = (r < Kv) ? *(const float2*)&Vg[r * 64 + 2 * c] : make_float2(0.f, 0.f);
        __half2 kh = __floats2half2_rn(kv.x, kv.y);
        __half2 vh = __floats2half2_rn(vv.x, vv.y);
        *(__half2*)(smem + SM_KH + r * 144 + 4 * c) = kh;
        int vb = (r >> 1) * 288 + (r & 1) * 2;       // key-pair interleave
        *(__half*)(smem + SM_VH + vb + 8 * c)     = __low2half(vh);
        *(__half*)(smem + SM_VH + vb + 8 * c + 4) = __high2half(vh);
    }
    __syncthreads();

    const int p  = p0 + pl;
    const int Wp = min(144, 2048 - (p + 1) * 16);   // 0 only for p=127
    const int obase = bh * 2048 + p * 16;
    const float scale = fminf(fmaxf(__expf(LS[0]), 1.f), 30.f) * 0.125f;

    // ---- Q fragments (hi/lo) straight from gmem ----
    const float* Qg = Q + (bh * 2048 + p * 16) * 64;
    uint32_t qh[4][4], ql[4][4];
    #pragma unroll
    for (int ks = 0; ks < 4; ks++) {
        #pragma unroll
        for (int q = 0; q < 4; q++) {
            int rr = (q & 1) ? g + 8 : g;
            int cc = 16 * ks + 2 * t + ((q >= 2) ? 8 : 0);
            float2 v = *(const float2*)&Qg[rr * 64 + cc];
            __half2 hh = __floats2half2_rn(v.x, v.y);
            float2 f = __half22float2(hh);
            __half2 ll = __floats2half2_rn(v.x - f.x, v.y - f.y);
            qh[ks][q] = *(uint32_t*)&hh;
            ql[ks][q] = *(uint32_t*)&ll;
        }
    }

    // ---- scores: this warp's 72-key half (<=9 n-tiles), 2 MMAs (Qhi,Qlo)·K ----
    const int nTl = max(0, min(9, (Wp - 72 * h) >> 3));
    float sD[9][4];
    #pragma unroll
    for (int i = 0; i < 9; i++) { sD[i][0] = sD[i][1] = sD[i][2] = sD[i][3] = 0.f; }
    const char* khp = smem + SM_KH + (16 * pl + 72 * h + g) * 144 + 4 * t;
    #pragma unroll
    for (int nt = 0; nt < 9; nt++) {
        if (nt < nTl) {
            #pragma unroll
            for (int ks = 0; ks < 4; ks++) {
                uint32_t bf[2];
                bf[0] = *(const uint32_t*)(khp + nt * 1152 + ks * 32);
                bf[1] = *(const uint32_t*)(khp + nt * 1152 + ks * 32 + 16);
                mma16816(sD[nt], qh[ks], bf);
                mma16816(sD[nt], ql[ks], bf);
            }
        }
    }

    // ---- partial row max/min (rows g, g+8), quad reduce ----
    float mx0 = -1e30f, mn0 = 1e30f, mx8 = -1e30f, mn8 = 1e30f;
    #pragma unroll
    for (int nt = 0; nt < 9; nt++) if (nt < nTl) {
        mx0 = fmaxf(mx0, fmaxf(sD[nt][0], sD[nt][1]));
        mn0 = fminf(mn0, fminf(sD[nt][0], sD[nt][1]));
        mx8 = fmaxf(mx8, fmaxf(sD[nt][2], sD[nt][3]));
        mn8 = fminf(mn8, fminf(sD[nt][2], sD[nt][3]));
    }
    #pragma unroll
    for (int o = 1; o <= 2; o <<= 1) {
        mx0 = fmaxf(mx0, __shfl_xor_sync(~0u, mx0, o));
        mn0 = fminf(mn0, __shfl_xor_sync(~0u, mn0, o));
        mx8 = fmaxf(mx8, __shfl_xor_sync(~0u, mx8, o));
        mn8 = fminf(mn8, __shfl_xor_sync(~0u, mn8, o));
    }
    // r1 exchange; __syncthreads doubles as "K dead" barrier for the A alias
    float2* r1w = (float2*)(smem + SM_ST + pl * 256 + h * 128);
    if (t == 0) { r1w[g] = make_float2(mx0, mn0); r1w[g + 8] = make_float2(mx8, mn8); }
    __syncthreads();
    {
        float2* r10 = (float2*)(smem + SM_ST + pl * 256);
        float2* r11 = (float2*)(smem + SM_ST + pl * 256 + 128);
        float2 a = r10[g],     b = r11[g];
        mx0 = fmaxf(a.x, b.x); mn0 = fminf(a.y, b.y);
        float2 c = r10[g + 8], d = r11[g + 8];
        mx8 = fmaxf(c.x, d.x); mn8 = fminf(c.y, d.y);
    }

    // ---- partial exp sums with global max/min ----
    float sp0 = 0.f, sn0 = 0.f, sp8 = 0.f, sn8 = 0.f;
    #pragma unroll
    for (int nt = 0; nt < 9; nt++) if (nt < nTl) {
        sp0 += __expf(scale * (sD[nt][0] - mx0)) + __expf(scale * (sD[nt][1] - mx0));
        sn0 += __expf(scale * (mn0 - sD[nt][0])) + __expf(scale * (mn0 - sD[nt][1]));
        sp8 += __expf(scale * (sD[nt][2] - mx8)) + __expf(scale * (sD[nt][3] - mx8));
        sn8 += __expf(scale * (mn8 - sD[nt][2])) + __expf(scale * (mn8 - sD[nt][3]));
    }
    #pragma unroll
    for (int o = 1; o <= 2; o <<= 1) {
        sp0 += __shfl_xor_sync(~0u, sp0, o);
        sn0 += __shfl_xor_sync(~0u, sn0, o);
        sp8 += __shfl_xor_sync(~0u, sp8, o);
        sn8 += __shfl_xor_sync(~0u, sn8, o);
    }
    float2* r2w = (float2*)(smem + SM_ST + 1024 + pl * 256 + h * 128);
    if (t == 0) { r2w[g] = make_float2(sp0, sn0); r2w[g + 8] = make_float2(sp8, sn8); }
    PAIR_BAR(1 + pl);
    float rp0, rn0, rp8, rn8;
    {
        float2* r20 = (float2*)(smem + SM_ST + 1024 + pl * 256);
        float2* r21 = (float2*)(smem + SM_ST + 1024 + pl * 256 + 128);
        float2 a = r20[g],     b = r21[g];
        rp0 = 1.0f / (a.x + b.x); rn0 = 1.0f / (a.y + b.y);
        float2 c = r20[g + 8], d = r21[g + 8];
        rp8 = 1.0f / (c.x + d.x); rn8 = 1.0f / (c.y + d.y);
    }

    // ---- write A (fp16, 2 keys/word) into dead-K region ----
    uint32_t* Apat = (uint32_t*)smem + pl * A_PATCH;
    #pragma unroll
    for (int nt = 0; nt < 9; nt++) if (nt < nTl) {
        float a0 = __expf(scale * (sD[nt][0] - mx0)) * rp0 - __expf(scale * (mn0 - sD[nt][0])) * rn0;
        float a1 = __expf(scale * (sD[nt][1] - mx0)) * rp0 - __expf(scale * (mn0 - sD[nt][1])) * rn0;
        float a2 = __expf(scale * (sD[nt][2] - mx8)) * rp8 - __expf(scale * (mn8 - sD[nt][2])) * rn8;
        float a3 = __expf(scale * (sD[nt][3] - mx8)) * rp8 - __expf(scale * (mn8 - sD[nt][3])) * rn8;
        int wc = 36 * h + 4 * nt + t;                 // packed word column
        Apat[g * A_STRIDE + wc]       = packA2(a0, a1);
        Apat[(g + 8) * A_STRIDE + wc] = packA2(a2, a3);
    }
    PAIR_BAR(1 + pl);    // A complete for this patch

    // ---- AV: all keys x this warp's 32-dim half; A-words ARE a-frags ----
    const int kSteps = max(0, Wp) >> 4;
    float oD[4][4];
    #pragma unroll
    for (int i = 0; i < 4; i++) { oD[i][0] = oD[i][1] = oD[i][2] = oD[i][3] = 0.f; }
    const char* vhp = smem + SM_VH + (8 * pl + t) * 288 + 4 * g + 128 * h;
    #pragma unroll
    for (int ks = 0; ks < 9; ks++) {
        if (ks < kSteps) {
            uint32_t a[4];
            a[0] = Apat[g * A_STRIDE + 8 * ks + t];
            a[1] = Apat[(g + 8) * A_STRIDE + 8 * ks + t];
            a[2] = Apat[g * A_STRIDE + 8 * ks + 4 + t];
            a[3] = Apat[(g + 8) * A_STRIDE + 8 * ks + 4 + t];
            #pragma unroll
            for (int j = 0; j < 4; j++) {
                uint32_t b[2];
                b[0] = *(const uint32_t*)(vhp + ks * 2304 + j * 32);
                b[1] = *(const uint32_t*)(vhp + ks * 2304 + j * 32 + 1152);
                mma16816(oD[j], a, b);
            }
        }
    }

    // ---- store O (this warp's 32 dims); zeros for p=127 ----
    #pragma unroll
    for (int j = 0; j < 4; j++) {
        int dbase = 8 * (4 * h + j) + 2 * t;
        *(float2*)&O[(obase + g) * 64 + dbase]     = make_float2(oD[j][0], oD[j][1]);
        *(float2*)&O[(obase + g + 8) * 64 + dbase] = make_float2(oD[j][2], oD[j][3]);
    }
}

extern "C" void kernel_launch(void* const* d_in, const int* in_sizes, int n_in,
                              void* d_out, int out_size)
{
    const float* Q  = (const float*)d_in[0];
    const float* K  = (const float*)d_in[1];
    const float* V  = (const float*)d_in[2];
    const float* ls = (const float*)d_in[3];
    float* O        = (float*)d_out;

    cudaFuncSetAttribute(signed_attn_hmma4,
                         cudaFuncAttributeMaxDynamicSharedMemorySize, SMEM_BYTES);

    dim3 grid(32, 32);   // 32 patch groups x 32 bh = 1024 CTAs
    signed_attn_hmma4<<<grid, 256, SMEM_BYTES>>>(Q, K, V, ls, O);
}